// round 1
// baseline (speedup 1.0000x reference)
#include <cuda_runtime.h>

// KSpaceMap: out[b,i,h,w] = Ar[b,h,i]*cos(2*pi*i*w/128)/128 - Ai[b,h,i]*sin(2*pi*i*w/128)/128
// where A = fft(x, axis=-1) (the ifft along H cancels the H-axis part of fft2).
// mask input is unused by the reference.

#define NB  32
#define NW  128   // W == H == 128
#define TWO_PI 6.28318530717958647692f

// 4 MB scratch for the row-DFT result, laid out [b][i][h] for coalesced reads in expand.
__device__ float g_Ar[NB * NW * NW];
__device__ float g_Ai[NB * NW * NW];

// Kernel 1: row DFT. block = (b*128 + h), thread = frequency i.
__global__ void __launch_bounds__(128) dft_rows(const float* __restrict__ x) {
    __shared__ float xr[NW];
    __shared__ float ct[NW];
    __shared__ float st[NW];

    const int bid = blockIdx.x;       // b*128 + h
    const int i   = threadIdx.x;      // frequency index

    float s, c;
    sincosf(TWO_PI * (float)i / (float)NW, &s, &c);
    ct[i] = c;
    st[i] = s;
    xr[i] = x[(size_t)bid * NW + i];
    __syncthreads();

    float ar = 0.0f, ai = 0.0f;
    int t = 0;                        // t = (i*w) mod 128, updated by recurrence
#pragma unroll 8
    for (int w = 0; w < NW; ++w) {
        const float xv = xr[w];
        ar = fmaf(xv, ct[t], ar);
        ai = fmaf(xv, st[t], ai);
        t = (t + i) & (NW - 1);
    }

    const int b = bid >> 7;
    const int h = bid & (NW - 1);
    // fft: real = sum x cos, imag = -sum x sin
    g_Ar[((size_t)b * NW + i) * NW + h] = ar;
    g_Ai[((size_t)b * NW + i) * NW + h] = -ai;
}

// Kernel 2: expansion (store-bound). block = (b*128 + i), 256 threads.
// thread t: w4 = t&31 (float4 column group), h0 = t>>5, h strides by 8 (16 iters).
__global__ void __launch_bounds__(256) expand(float4* __restrict__ out) {
    __shared__ float sAr[NW];
    __shared__ float sAi[NW];
    __shared__ float sc[NW];
    __shared__ float ss[NW];

    const int bid = blockIdx.x;       // b*128 + i
    const int i   = bid & (NW - 1);
    const int tid = threadIdx.x;

    if (tid < NW) {
        sAr[tid] = g_Ar[(size_t)bid * NW + tid];
        sAi[tid] = g_Ai[(size_t)bid * NW + tid];
    } else {
        const int w = tid - NW;
        const int t = (i * w) & (NW - 1);
        float s, c;
        sincosf(TWO_PI * (float)t / (float)NW, &s, &c);
        sc[w] = c * (1.0f / (float)NW);
        ss[w] = s * (1.0f / (float)NW);
    }
    __syncthreads();

    const int w4 = tid & 31;          // float4 group: covers w = 4*w4 .. 4*w4+3
    const int h0 = tid >> 5;          // 0..7

    const float c0 = sc[4 * w4 + 0], c1 = sc[4 * w4 + 1];
    const float c2 = sc[4 * w4 + 2], c3 = sc[4 * w4 + 3];
    const float s0 = ss[4 * w4 + 0], s1 = ss[4 * w4 + 1];
    const float s2 = ss[4 * w4 + 2], s3 = ss[4 * w4 + 3];

    float4* __restrict__ obase = out + (size_t)bid * (NW * (NW / 4)) + w4;

#pragma unroll
    for (int h = h0; h < NW; h += 8) {
        const float ar = sAr[h];
        const float ai = sAi[h];
        float4 o;
        o.x = fmaf(ar, c0, -ai * s0);
        o.y = fmaf(ar, c1, -ai * s1);
        o.z = fmaf(ar, c2, -ai * s2);
        o.w = fmaf(ar, c3, -ai * s3);
        obase[(size_t)h * (NW / 4)] = o;
    }
}

extern "C" void kernel_launch(void* const* d_in, const int* in_sizes, int n_in,
                              void* d_out, int out_size) {
    // input is (32,1,128,128) = 524288 elems; mask is (32,1,1,128) = 4096 and unused.
    const float* x = (const float*)d_in[0];
    if (in_sizes[0] != NB * NW * NW && n_in > 1) {
        x = (const float*)d_in[1];
    }
    dft_rows<<<NB * NW, 128>>>(x);
    expand<<<NB * NW, 256>>>((float4*)d_out);
}